// round 6
// baseline (speedup 1.0000x reference)
#include <cuda_runtime.h>
#include <cuda_fp16.h>
#include <math.h>

// 3-layer GCN. Pull-style aggregation over a per-launch CSR (no feature atomics).
//   G(half) = (dis * act(X)) @ W      [W-in-registers f32x2 GEMM, 1 col/thread]
//   S[i] = b + dis[i] * (G[i] + sum_{dst=i} G[src])   (fp32 accum)
//   layer1 out stored as relu'd fp16; layer2 out fp32.
//   out = log_softmax(relu(S2) @ W3 + b3), plus h = relu(S2)

#define MAX_N 100000
#define MAX_E 1600000
#define NPAD  100352

__device__ int    g_count[NPAD];
__device__ int    g_rowstart[NPAD];
__device__ int    g_cursor[NPAD];
__device__ float  g_dis[NPAD];
__device__ int    g_sums[32];
__device__ int    g_flag[32];
__device__ int    g_esrc[MAX_E];
__device__ __half g_Gh[MAX_N * 64];
__device__ __half g_S1h[MAX_N * 64];
__device__ float  g_S2[MAX_N * 64];

typedef unsigned long long ull;

__device__ __forceinline__ void ffma2(ull& acc, ull x, ull w) {
    asm("fma.rn.f32x2 %0, %1, %2, %0;" : "+l"(acc) : "l"(x), "l"(w));
}
__device__ __forceinline__ void fadd2(ull& a, ull b) {
    asm("add.rn.f32x2 %0, %0, %1;" : "+l"(a) : "l"(b));
}
__device__ __forceinline__ ull pack_dup(float v) {
    ull r;
    asm("mov.b64 %0, {%1, %1};" : "=l"(r) : "r"(__float_as_uint(v)));
    return r;
}
__device__ __forceinline__ ull h2_to_f2(unsigned int h) {
    __half2 hh = *reinterpret_cast<__half2*>(&h);
    float2 f = __half22float2(hh);
    return *reinterpret_cast<ull*>(&f);
}

// ---------------- CSR build ----------------

__global__ void k_count(const int* __restrict__ dst, int e) {
    int i4 = (blockIdx.x * blockDim.x + threadIdx.x) * 4;
    if (i4 + 3 < e) {
        int4 d = *(const int4*)&dst[i4];
        atomicAdd(&g_count[d.x], 1);
        atomicAdd(&g_count[d.y], 1);
        atomicAdd(&g_count[d.z], 1);
        atomicAdd(&g_count[d.w], 1);
    } else {
        for (int i = i4; i < e; i++) atomicAdd(&g_count[dst[i]], 1);
    }
}

// Single-kernel exclusive scan over counts (all nb<=25 blocks resident).
__global__ void k_scan(int n) {
    __shared__ int sh[1024];
    __shared__ int s_prev;
    int b = blockIdx.x, t = threadIdx.x;
    int base = b * 4096 + t * 4;
    int v0 = 0, v1 = 0, v2 = 0, v3 = 0;
    if (base + 3 < n) {
        int4 v = *(const int4*)&g_count[base];
        v0 = v.x; v1 = v.y; v2 = v.z; v3 = v.w;
    } else {
        if (base     < n) v0 = g_count[base];
        if (base + 1 < n) v1 = g_count[base + 1];
        if (base + 2 < n) v2 = g_count[base + 2];
    }
    int local = v0 + v1 + v2 + v3;
    sh[t] = local;
    __syncthreads();
    for (int off = 1; off < 1024; off <<= 1) {
        int x = (t >= off) ? sh[t - off] : 0;
        __syncthreads();
        sh[t] += x;
        __syncthreads();
    }
    if (t == 1023) {
        g_sums[b] = sh[1023];
        __threadfence();
        atomicExch(&g_flag[b], 1);
    }
    if (t < 32) {
        int p = 0;
        for (int i = t; i < b; i += 32) {
            while (atomicAdd(&g_flag[i], 0) == 0) { }
            p += atomicAdd(&g_sums[i], 0);
        }
#pragma unroll
        for (int o = 16; o; o >>= 1) p += __shfl_xor_sync(0xffffffffu, p, o);
        if (t == 0) s_prev = p;
    }
    int excl = sh[t] - local;
    __syncthreads();
    int run = s_prev + excl;
    if (base < n) {
        g_rowstart[base] = run; g_cursor[base] = run;
        g_dis[base] = rsqrtf((float)(v0 + 1)); run += v0;
    }
    if (base + 1 < n) {
        g_rowstart[base + 1] = run; g_cursor[base + 1] = run;
        g_dis[base + 1] = rsqrtf((float)(v1 + 1)); run += v1;
    }
    if (base + 2 < n) {
        g_rowstart[base + 2] = run; g_cursor[base + 2] = run;
        g_dis[base + 2] = rsqrtf((float)(v2 + 1)); run += v2;
    }
    if (base + 3 < n) {
        g_rowstart[base + 3] = run; g_cursor[base + 3] = run;
        g_dis[base + 3] = rsqrtf((float)(v3 + 1));
    }
}

__global__ void k_fill(const int* __restrict__ src, const int* __restrict__ dst, int e) {
    int i4 = (blockIdx.x * blockDim.x + threadIdx.x) * 4;
    if (i4 + 3 < e) {
        int4 s = *(const int4*)&src[i4];
        int4 d = *(const int4*)&dst[i4];
        g_esrc[atomicAdd(&g_cursor[d.x], 1)] = s.x;
        g_esrc[atomicAdd(&g_cursor[d.y], 1)] = s.y;
        g_esrc[atomicAdd(&g_cursor[d.z], 1)] = s.z;
        g_esrc[atomicAdd(&g_cursor[d.w], 1)] = s.w;
    } else {
        for (int i = i4; i < e; i++)
            g_esrc[atomicAdd(&g_cursor[dst[i]], 1)] = src[i];
    }
}

// ---------------- GEMM: G(half)[row] = (dis[row]*X[row]) @ W ----------------
// Thread owns ONE column c = lane + 32*(w&1) for all k (wf[64] = 64 regs) and
// 16 rows (8 f32x2 row-pair accumulators). X tile (64 rows) staged transposed,
// dis-scaled, in 16 KB smem. Per k: 4 broadcast LDS.128 + 1 dup-mov + 8 FFMA2.
// 2 blocks/SM (launch_bounds), persistent grid, reg-prefetch of next tile.

template <bool HALF_IN>
__global__ void __launch_bounds__(256, 2)
k_gemm64(const void* __restrict__ Xp, const float* __restrict__ W,
         __half* __restrict__ G, int n) {
    __shared__ float xst[64 * 64];   // 16 KB  xst[k*64 + r], dis-scaled

    int tid  = threadIdx.x;
    int lane = tid & 31;
    int wid  = tid >> 5;
    int c    = lane + 32 * (wid & 1);
    int r0   = (wid >> 1) * 16;

    // W column c for all k (64 regs).
    float wf[64];
#pragma unroll
    for (int k = 0; k < 64; k++) wf[k] = W[k * 64 + c];

    int ntiles = (n + 63) >> 6;
    int r   = tid & 63;   // staging row within tile
    int kgb = tid >> 6;   // staging k-chunk (16 ks)

    const float4* Xf = (const float4*)Xp;
    const uint4*  Xh = (const uint4*)Xp;

    float4 pf[4];
    uint4  ph[2];
    float  pd = 0.f;

    // prefetch first tile
    {
        int row = (blockIdx.x << 6) + r;
        if (row < n) {
            pd = g_dis[row];
            if (HALF_IN) {
                ph[0] = Xh[(size_t)row * 8 + kgb * 2];
                ph[1] = Xh[(size_t)row * 8 + kgb * 2 + 1];
            } else {
#pragma unroll
                for (int j = 0; j < 4; j++) pf[j] = Xf[(size_t)row * 16 + kgb * 4 + j];
            }
        } else {
            pd = 0.f;
            if (HALF_IN) { ph[0] = make_uint4(0,0,0,0); ph[1] = make_uint4(0,0,0,0); }
            else {
#pragma unroll
                for (int j = 0; j < 4; j++) pf[j] = make_float4(0.f,0.f,0.f,0.f);
            }
        }
    }

    for (int tile = blockIdx.x; tile < ntiles; tile += gridDim.x) {
        int rowbase = tile << 6;
        __syncthreads();   // previous compute done
        if (HALF_IN) {
#pragma unroll
            for (int u = 0; u < 2; u++) {
                const unsigned int* pw = (const unsigned int*)&ph[u];
#pragma unroll
                for (int m = 0; m < 4; m++) {
                    float2 f = __half22float2(*reinterpret_cast<const __half2*>(&pw[m]));
                    int k = kgb * 16 + u * 8 + m * 2;
                    xst[(k + 0) * 64 + r] = f.x * pd;
                    xst[(k + 1) * 64 + r] = f.y * pd;
                }
            }
        } else {
#pragma unroll
            for (int j = 0; j < 4; j++) {
                float4 v = pf[j];
                int k = kgb * 16 + j * 4;
                xst[(k + 0) * 64 + r] = v.x * pd;
                xst[(k + 1) * 64 + r] = v.y * pd;
                xst[(k + 2) * 64 + r] = v.z * pd;
                xst[(k + 3) * 64 + r] = v.w * pd;
            }
        }
        __syncthreads();   // tile staged

        // prefetch next tile while computing
        int tn = tile + gridDim.x;
        if (tn < ntiles) {
            int row = (tn << 6) + r;
            if (row < n) {
                pd = g_dis[row];
                if (HALF_IN) {
                    ph[0] = Xh[(size_t)row * 8 + kgb * 2];
                    ph[1] = Xh[(size_t)row * 8 + kgb * 2 + 1];
                } else {
#pragma unroll
                    for (int j = 0; j < 4; j++) pf[j] = Xf[(size_t)row * 16 + kgb * 4 + j];
                }
            } else {
                pd = 0.f;
                if (HALF_IN) { ph[0] = make_uint4(0,0,0,0); ph[1] = make_uint4(0,0,0,0); }
                else {
#pragma unroll
                    for (int j = 0; j < 4; j++) pf[j] = make_float4(0.f,0.f,0.f,0.f);
                }
            }
        }

        ull acc[8];
#pragma unroll
        for (int p = 0; p < 8; p++) acc[p] = 0;

#pragma unroll
        for (int k = 0; k < 64; k++) {
            const ulonglong2* xp = (const ulonglong2*)&xst[k * 64 + r0];
            ulonglong2 xa = xp[0];
            ulonglong2 xb = xp[1];
            ulonglong2 xc = xp[2];
            ulonglong2 xd = xp[3];
            ull wd = pack_dup(wf[k]);
            ffma2(acc[0], xa.x, wd); ffma2(acc[1], xa.y, wd);
            ffma2(acc[2], xb.x, wd); ffma2(acc[3], xb.y, wd);
            ffma2(acc[4], xc.x, wd); ffma2(acc[5], xc.y, wd);
            ffma2(acc[6], xd.x, wd); ffma2(acc[7], xd.y, wd);
        }

#pragma unroll
        for (int p = 0; p < 8; p++) {
            float2 v = *reinterpret_cast<float2*>(&acc[p]);
            int row = rowbase + r0 + 2 * p;
            if (row < n)     G[(size_t)row * 64 + c]       = __float2half_rn(v.x);
            if (row + 1 < n) G[(size_t)(row + 1) * 64 + c] = __float2half_rn(v.y);
        }
    }
}

// ---------------- Aggregation: 1 warp/node; 8 lanes x 16B, 4-edge ILP ----------------
// HALF_OUT: apply relu and store fp16 (layer-1 output). Else fp32.

template <bool HALF_OUT>
__global__ void k_agg(const __half* __restrict__ G, const float* __restrict__ bias,
                      void* __restrict__ Sp, int n) {
    int warp = (blockIdx.x * blockDim.x + threadIdx.x) >> 5;
    if (warp >= n) return;
    int node = warp;
    int lane = threadIdx.x & 31;
    int q  = lane & 7;    // 16-byte feature chunk (8 halves)
    int pe = lane >> 3;   // 0..3 edge phase

    const uint4* __restrict__ Gv = (const uint4*)G;
    ull acc0 = 0, acc1 = 0, acc2 = 0, acc3 = 0;

    if (pe == 0) {
        uint4 v = Gv[(size_t)node * 8 + q];   // self-loop term
        acc0 = h2_to_f2(v.x); acc1 = h2_to_f2(v.y);
        acc2 = h2_to_f2(v.z); acc3 = h2_to_f2(v.w);
    }

    int s   = g_rowstart[node];
    int end = s + g_count[node];
    for (int p = s + pe; p < end; p += 4) {
        int j = g_esrc[p];
        uint4 v = Gv[(size_t)j * 8 + q];
        fadd2(acc0, h2_to_f2(v.x));
        fadd2(acc1, h2_to_f2(v.y));
        fadd2(acc2, h2_to_f2(v.z));
        fadd2(acc3, h2_to_f2(v.w));
    }

#pragma unroll
    for (int o = 8; o <= 16; o <<= 1) {
        fadd2(acc0, __shfl_xor_sync(0xffffffffu, acc0, o));
        fadd2(acc1, __shfl_xor_sync(0xffffffffu, acc1, o));
        fadd2(acc2, __shfl_xor_sync(0xffffffffu, acc2, o));
        fadd2(acc3, __shfl_xor_sync(0xffffffffu, acc3, o));
    }

    if (pe == 0) {
        float d = g_dis[node];
        float2 f0 = *reinterpret_cast<float2*>(&acc0);
        float2 f1 = *reinterpret_cast<float2*>(&acc1);
        float2 f2 = *reinterpret_cast<float2*>(&acc2);
        float2 f3 = *reinterpret_cast<float2*>(&acc3);
        const float4* Bv = (const float4*)bias;
        float4 b0 = Bv[q * 2], b1 = Bv[q * 2 + 1];
        float o0 = fmaf(d, f0.x, b0.x), o1 = fmaf(d, f0.y, b0.y);
        float o2 = fmaf(d, f1.x, b0.z), o3 = fmaf(d, f1.y, b0.w);
        float o4 = fmaf(d, f2.x, b1.x), o5 = fmaf(d, f2.y, b1.y);
        float o6 = fmaf(d, f3.x, b1.z), o7 = fmaf(d, f3.y, b1.w);
        if (HALF_OUT) {
            // relu folded in (layer-1 output feeds layer-2 GEMM)
            uint4 hv;
            __half2 h0 = __floats2half2_rn(fmaxf(o0, 0.f), fmaxf(o1, 0.f));
            __half2 h1 = __floats2half2_rn(fmaxf(o2, 0.f), fmaxf(o3, 0.f));
            __half2 h2 = __floats2half2_rn(fmaxf(o4, 0.f), fmaxf(o5, 0.f));
            __half2 h3 = __floats2half2_rn(fmaxf(o6, 0.f), fmaxf(o7, 0.f));
            hv.x = *reinterpret_cast<unsigned int*>(&h0);
            hv.y = *reinterpret_cast<unsigned int*>(&h1);
            hv.z = *reinterpret_cast<unsigned int*>(&h2);
            hv.w = *reinterpret_cast<unsigned int*>(&h3);
            ((uint4*)Sp)[(size_t)node * 8 + q] = hv;
        } else {
            float4* Sv = (float4*)Sp;
            Sv[(size_t)node * 16 + q * 2]     = make_float4(o0, o1, o2, o3);
            Sv[(size_t)node * 16 + q * 2 + 1] = make_float4(o4, o5, o6, o7);
        }
    }
}

// ---------------- Final: h = relu(S2); z = h@W3 + b3; log_softmax ----------------

__global__ void k_final(const float* __restrict__ S2, const float* __restrict__ W3,
                        const float* __restrict__ b3, float* __restrict__ out,
                        int n, int write_h) {
    __shared__ float w3s[64 * 16];
    __shared__ float b3s[16];
    for (int i = threadIdx.x; i < 64 * 16; i += blockDim.x) w3s[i] = W3[i];
    if (threadIdx.x < 16) b3s[threadIdx.x] = b3[threadIdx.x];
    __syncthreads();

    int row = blockIdx.x * blockDim.x + threadIdx.x;
    if (row >= n) return;

    float h[64];
    const float4* Sv = (const float4*)(S2 + (size_t)row * 64);
#pragma unroll
    for (int i = 0; i < 16; i++) {
        float4 v = Sv[i];
        h[4 * i + 0] = fmaxf(v.x, 0.0f);
        h[4 * i + 1] = fmaxf(v.y, 0.0f);
        h[4 * i + 2] = fmaxf(v.z, 0.0f);
        h[4 * i + 3] = fmaxf(v.w, 0.0f);
    }

    if (write_h) {
        float4* Hv = (float4*)(out + (size_t)n * 16 + (size_t)row * 64);
#pragma unroll
        for (int i = 0; i < 16; i++) {
            float4 v;
            v.x = h[4 * i + 0]; v.y = h[4 * i + 1];
            v.z = h[4 * i + 2]; v.w = h[4 * i + 3];
            Hv[i] = v;
        }
    }

    float z[16];
#pragma unroll
    for (int j = 0; j < 16; j++) z[j] = b3s[j];
#pragma unroll
    for (int k = 0; k < 64; k++) {
        float xv = h[k];
#pragma unroll
        for (int j = 0; j < 16; j++) z[j] = fmaf(xv, w3s[k * 16 + j], z[j]);
    }

    float m = z[0];
#pragma unroll
    for (int j = 1; j < 16; j++) m = fmaxf(m, z[j]);
    float ssum = 0.0f;
#pragma unroll
    for (int j = 0; j < 16; j++) ssum += __expf(z[j] - m);
    float lse = m + __logf(ssum);
#pragma unroll
    for (int j = 0; j < 16; j++) out[(size_t)row * 16 + j] = z[j] - lse;
}

// ---------------- launch ----------------

extern "C" void kernel_launch(void* const* d_in, const int* in_sizes, int n_in,
                              void* d_out, int out_size) {
    const float* x  = (const float*)d_in[0];
    const int*   ei = (const int*)d_in[1];
    const float* W1 = (const float*)d_in[2];
    const float* b1 = (const float*)d_in[3];
    const float* W2 = (const float*)d_in[4];
    const float* b2 = (const float*)d_in[5];
    const float* W3 = (const float*)d_in[6];
    const float* b3 = (const float*)d_in[7];
    float* out = (float*)d_out;

    int n = in_sizes[0] / 64;
    int e = in_sizes[1] / 2;
    const int* src = ei;
    const int* dst = ei + e;
    int write_h = (out_size >= n * 80) ? 1 : 0;

    void* cnt_p;  cudaGetSymbolAddress(&cnt_p,  g_count);
    void* flag_p; cudaGetSymbolAddress(&flag_p, g_flag);
    __half* G  = nullptr; cudaGetSymbolAddress((void**)&G,  g_Gh);
    __half* S1 = nullptr; cudaGetSymbolAddress((void**)&S1, g_S1h);
    float*  S2 = nullptr; cudaGetSymbolAddress((void**)&S2, g_S2);

    int nb = (n + 4095) / 4096;
    int e4blocks = ((e + 3) / 4 + 255) / 256;

    cudaMemsetAsync(cnt_p,  0, (size_t)n * sizeof(int));
    cudaMemsetAsync(flag_p, 0, 32 * sizeof(int));
    k_count<<<e4blocks, 256>>>(dst, e);
    k_scan<<<nb, 1024>>>(n);
    k_fill<<<e4blocks, 256>>>(src, dst, e);

    k_gemm64<false><<<296, 256>>>(x, W1, G, n);
    k_agg<true><<<(n * 32 + 255) / 256, 256>>>(G, b1, S1, n);
    k_gemm64<true><<<296, 256>>>(S1, W2, G, n);
    k_agg<false><<<(n * 32 + 255) / 256, 256>>>(G, b2, S2, n);
    k_final<<<(n + 255) / 256, 256>>>(S2, W3, b3, out, n, write_h);
}

// round 7
// speedup vs baseline: 1.1024x; 1.1024x over previous
#include <cuda_runtime.h>
#include <cuda_fp16.h>
#include <math.h>

// 3-layer GCN. Pull-style aggregation over a per-launch CSR (no feature atomics).
//   G(half) = (dis * act(X)) @ W      [tensor-core HMMA m16n8k16, fp32 accum]
//   S[i] = b + dis[i] * (G[i] + sum_{dst=i} G[src])   (fp32 accum)
//   layer1 out stored as relu'd fp16; layer2 out fp32.
//   out = log_softmax(relu(S2) @ W3 + b3), plus h = relu(S2)

#define MAX_N 100000
#define MAX_E 1600000
#define NPAD  100352

__device__ int    g_count[NPAD];
__device__ int    g_rowstart[NPAD];
__device__ int    g_cursor[NPAD];
__device__ float  g_dis[NPAD];
__device__ int    g_sums[32];
__device__ int    g_flag[32];
__device__ int    g_esrc[MAX_E];
__device__ __half g_Gh[MAX_N * 64];
__device__ __half g_S1h[MAX_N * 64];
__device__ float  g_S2[MAX_N * 64];

typedef unsigned long long ull;

__device__ __forceinline__ void fadd2(ull& a, ull b) {
    asm("add.rn.f32x2 %0, %0, %1;" : "+l"(a) : "l"(b));
}
__device__ __forceinline__ ull h2_to_f2(unsigned int h) {
    __half2 hh = *reinterpret_cast<__half2*>(&h);
    float2 f = __half22float2(hh);
    return *reinterpret_cast<ull*>(&f);
}

// ---------------- CSR build ----------------

__global__ void k_count(const int* __restrict__ dst, int e) {
    int i4 = (blockIdx.x * blockDim.x + threadIdx.x) * 4;
    if (i4 + 3 < e) {
        int4 d = *(const int4*)&dst[i4];
        atomicAdd(&g_count[d.x], 1);
        atomicAdd(&g_count[d.y], 1);
        atomicAdd(&g_count[d.z], 1);
        atomicAdd(&g_count[d.w], 1);
    } else {
        for (int i = i4; i < e; i++) atomicAdd(&g_count[dst[i]], 1);
    }
}

// Single-kernel exclusive scan over counts (all nb<=25 blocks resident).
__global__ void k_scan(int n) {
    __shared__ int sh[1024];
    __shared__ int s_prev;
    int b = blockIdx.x, t = threadIdx.x;
    int base = b * 4096 + t * 4;
    int v0 = 0, v1 = 0, v2 = 0, v3 = 0;
    if (base + 3 < n) {
        int4 v = *(const int4*)&g_count[base];
        v0 = v.x; v1 = v.y; v2 = v.z; v3 = v.w;
    } else {
        if (base     < n) v0 = g_count[base];
        if (base + 1 < n) v1 = g_count[base + 1];
        if (base + 2 < n) v2 = g_count[base + 2];
    }
    int local = v0 + v1 + v2 + v3;
    sh[t] = local;
    __syncthreads();
    for (int off = 1; off < 1024; off <<= 1) {
        int x = (t >= off) ? sh[t - off] : 0;
        __syncthreads();
        sh[t] += x;
        __syncthreads();
    }
    if (t == 1023) {
        g_sums[b] = sh[1023];
        __threadfence();
        atomicExch(&g_flag[b], 1);
    }
    if (t < 32) {
        int p = 0;
        for (int i = t; i < b; i += 32) {
            while (atomicAdd(&g_flag[i], 0) == 0) { }
            p += atomicAdd(&g_sums[i], 0);
        }
#pragma unroll
        for (int o = 16; o; o >>= 1) p += __shfl_xor_sync(0xffffffffu, p, o);
        if (t == 0) s_prev = p;
    }
    int excl = sh[t] - local;
    __syncthreads();
    int run = s_prev + excl;
    if (base < n) {
        g_rowstart[base] = run; g_cursor[base] = run;
        g_dis[base] = rsqrtf((float)(v0 + 1)); run += v0;
    }
    if (base + 1 < n) {
        g_rowstart[base + 1] = run; g_cursor[base + 1] = run;
        g_dis[base + 1] = rsqrtf((float)(v1 + 1)); run += v1;
    }
    if (base + 2 < n) {
        g_rowstart[base + 2] = run; g_cursor[base + 2] = run;
        g_dis[base + 2] = rsqrtf((float)(v2 + 1)); run += v2;
    }
    if (base + 3 < n) {
        g_rowstart[base + 3] = run; g_cursor[base + 3] = run;
        g_dis[base + 3] = rsqrtf((float)(v3 + 1));
    }
}

__global__ void k_fill(const int* __restrict__ src, const int* __restrict__ dst, int e) {
    int i4 = (blockIdx.x * blockDim.x + threadIdx.x) * 4;
    if (i4 + 3 < e) {
        int4 s = *(const int4*)&src[i4];
        int4 d = *(const int4*)&dst[i4];
        g_esrc[atomicAdd(&g_cursor[d.x], 1)] = s.x;
        g_esrc[atomicAdd(&g_cursor[d.y], 1)] = s.y;
        g_esrc[atomicAdd(&g_cursor[d.z], 1)] = s.z;
        g_esrc[atomicAdd(&g_cursor[d.w], 1)] = s.w;
    } else {
        for (int i = i4; i < e; i++)
            g_esrc[atomicAdd(&g_cursor[dst[i]], 1)] = src[i];
    }
}

// ---------------- GEMM (tensor core): G(half) = (dis*X) @ W ----------------
// Block = 256 thr / 8 warps, tile = 128 rows (16 rows/warp).
// X tile staged fp16 in smem, row stride 72 halves (conflict-free A loads).
// W fragments prebuilt in registers (64 regs/thread). Per kstep: 4 LDS.32
// + 8 HMMA m16n8k16 (fp32 accum). Epilogue: half2 STG.32.

template <bool HALF_IN>
__global__ void __launch_bounds__(256, 2)
k_gemm_mma(const void* __restrict__ Xp, const float* __restrict__ W,
           __half* __restrict__ G, int n) {
    __shared__ __half ws[64 * 64];    // 8 KB
    __shared__ __half xs[128 * 72];   // 18 KB

    int tid  = threadIdx.x;
    int lane = tid & 31;
    int w    = tid >> 5;

    // Stage W as half
    for (int i = tid; i < 4096; i += 256) ws[i] = __float2half_rn(W[i]);
    __syncthreads();

    // Build B fragments: thread holds col n = nt*8 + lane/4,
    // k rows (lane%4)*2 (+1), +8 (+9), per kstep.
    unsigned bfr[4][8][2];
    {
        int nq = lane >> 2;
        int kq = (lane & 3) * 2;
#pragma unroll
        for (int ks = 0; ks < 4; ks++) {
#pragma unroll
            for (int nt = 0; nt < 8; nt++) {
                int k  = ks * 16 + kq;
                int nn = nt * 8 + nq;
                __half2 b0 = __halves2half2(ws[k * 64 + nn],       ws[(k + 1) * 64 + nn]);
                __half2 b1 = __halves2half2(ws[(k + 8) * 64 + nn], ws[(k + 9) * 64 + nn]);
                bfr[ks][nt][0] = *reinterpret_cast<unsigned*>(&b0);
                bfr[ks][nt][1] = *reinterpret_cast<unsigned*>(&b1);
            }
        }
    }

    int ntiles = (n + 127) >> 7;
    int srow = tid >> 1;        // staging row within tile
    int sseg = tid & 1;         // staging half-row (32 cols)

    const float4* Xf = (const float4*)Xp;
    const uint4*  Xh = (const uint4*)Xp;

    for (int tile = blockIdx.x; tile < ntiles; tile += gridDim.x) {
        int rowbase = tile << 7;
        __syncthreads();   // xs free

        // ---- stage X tile (dis-scaled, fp16) ----
        int grow = rowbase + srow;
        float d = (grow < n) ? g_dis[grow] : 0.f;
        if (HALF_IN) {
#pragma unroll
            for (int u = 0; u < 4; u++) {
                uint4 v = (grow < n) ? Xh[(size_t)grow * 8 + sseg * 4 + u]
                                     : make_uint4(0, 0, 0, 0);
                const unsigned* pv = (const unsigned*)&v;
#pragma unroll
                for (int m = 0; m < 4; m++) {
                    float2 f = __half22float2(*reinterpret_cast<const __half2*>(&pv[m]));
                    __half2 h = __floats2half2_rn(f.x * d, f.y * d);
                    *reinterpret_cast<unsigned*>(&xs[srow * 72 + sseg * 32 + u * 8 + m * 2]) =
                        *reinterpret_cast<unsigned*>(&h);
                }
            }
        } else {
#pragma unroll
            for (int u = 0; u < 8; u++) {
                float4 v = (grow < n) ? Xf[(size_t)grow * 16 + sseg * 8 + u]
                                      : make_float4(0.f, 0.f, 0.f, 0.f);
                __half2 h0 = __floats2half2_rn(v.x * d, v.y * d);
                __half2 h1 = __floats2half2_rn(v.z * d, v.w * d);
                *reinterpret_cast<unsigned*>(&xs[srow * 72 + sseg * 32 + u * 4]) =
                    *reinterpret_cast<unsigned*>(&h0);
                *reinterpret_cast<unsigned*>(&xs[srow * 72 + sseg * 32 + u * 4 + 2]) =
                    *reinterpret_cast<unsigned*>(&h1);
            }
        }
        __syncthreads();   // tile staged

        // ---- compute: warp w owns rows w*16 .. w*16+15 ----
        float c[8][4];
#pragma unroll
        for (int nt = 0; nt < 8; nt++) {
            c[nt][0] = 0.f; c[nt][1] = 0.f; c[nt][2] = 0.f; c[nt][3] = 0.f;
        }

        int ar = w * 16 + (lane >> 2);
        int ak = (lane & 3) * 2;
#pragma unroll
        for (int ks = 0; ks < 4; ks++) {
            const __half* xb = &xs[ar * 72 + ks * 16 + ak];
            unsigned a0 = *reinterpret_cast<const unsigned*>(xb);
            unsigned a1 = *reinterpret_cast<const unsigned*>(xb + 8 * 72);
            unsigned a2 = *reinterpret_cast<const unsigned*>(xb + 8);
            unsigned a3 = *reinterpret_cast<const unsigned*>(xb + 8 * 72 + 8);
#pragma unroll
            for (int nt = 0; nt < 8; nt++) {
                asm volatile(
                    "mma.sync.aligned.m16n8k16.row.col.f32.f16.f16.f32 "
                    "{%0,%1,%2,%3}, {%4,%5,%6,%7}, {%8,%9}, {%0,%1,%2,%3};"
                    : "+f"(c[nt][0]), "+f"(c[nt][1]), "+f"(c[nt][2]), "+f"(c[nt][3])
                    : "r"(a0), "r"(a1), "r"(a2), "r"(a3),
                      "r"(bfr[ks][nt][0]), "r"(bfr[ks][nt][1]));
            }
        }

        // ---- epilogue ----
        int row0 = rowbase + w * 16 + (lane >> 2);
        int coln = (lane & 3) * 2;
#pragma unroll
        for (int nt = 0; nt < 8; nt++) {
            __half2 hlo = __floats2half2_rn(c[nt][0], c[nt][1]);
            __half2 hhi = __floats2half2_rn(c[nt][2], c[nt][3]);
            if (row0 < n)
                *reinterpret_cast<unsigned*>(&G[(size_t)row0 * 64 + nt * 8 + coln]) =
                    *reinterpret_cast<unsigned*>(&hlo);
            if (row0 + 8 < n)
                *reinterpret_cast<unsigned*>(&G[(size_t)(row0 + 8) * 64 + nt * 8 + coln]) =
                    *reinterpret_cast<unsigned*>(&hhi);
        }
    }
}

// ---------------- Aggregation: 1 warp/node; 8 lanes x 16B, 4-edge ILP ----------------
// HALF_OUT: apply relu and store fp16 (layer-1 output). Else fp32.

template <bool HALF_OUT>
__global__ void k_agg(const __half* __restrict__ G, const float* __restrict__ bias,
                      void* __restrict__ Sp, int n) {
    int warp = (blockIdx.x * blockDim.x + threadIdx.x) >> 5;
    if (warp >= n) return;
    int node = warp;
    int lane = threadIdx.x & 31;
    int q  = lane & 7;    // 16-byte feature chunk (8 halves)
    int pe = lane >> 3;   // 0..3 edge phase

    const uint4* __restrict__ Gv = (const uint4*)G;
    ull acc0 = 0, acc1 = 0, acc2 = 0, acc3 = 0;

    if (pe == 0) {
        uint4 v = Gv[(size_t)node * 8 + q];   // self-loop term
        acc0 = h2_to_f2(v.x); acc1 = h2_to_f2(v.y);
        acc2 = h2_to_f2(v.z); acc3 = h2_to_f2(v.w);
    }

    int s   = g_rowstart[node];
    int end = s + g_count[node];
    for (int p = s + pe; p < end; p += 4) {
        int j = g_esrc[p];
        uint4 v = Gv[(size_t)j * 8 + q];
        fadd2(acc0, h2_to_f2(v.x));
        fadd2(acc1, h2_to_f2(v.y));
        fadd2(acc2, h2_to_f2(v.z));
        fadd2(acc3, h2_to_f2(v.w));
    }

#pragma unroll
    for (int o = 8; o <= 16; o <<= 1) {
        fadd2(acc0, __shfl_xor_sync(0xffffffffu, acc0, o));
        fadd2(acc1, __shfl_xor_sync(0xffffffffu, acc1, o));
        fadd2(acc2, __shfl_xor_sync(0xffffffffu, acc2, o));
        fadd2(acc3, __shfl_xor_sync(0xffffffffu, acc3, o));
    }

    if (pe == 0) {
        float d = g_dis[node];
        float2 f0 = *reinterpret_cast<float2*>(&acc0);
        float2 f1 = *reinterpret_cast<float2*>(&acc1);
        float2 f2 = *reinterpret_cast<float2*>(&acc2);
        float2 f3 = *reinterpret_cast<float2*>(&acc3);
        const float4* Bv = (const float4*)bias;
        float4 b0 = Bv[q * 2], b1 = Bv[q * 2 + 1];
        float o0 = fmaf(d, f0.x, b0.x), o1 = fmaf(d, f0.y, b0.y);
        float o2 = fmaf(d, f1.x, b0.z), o3 = fmaf(d, f1.y, b0.w);
        float o4 = fmaf(d, f2.x, b1.x), o5 = fmaf(d, f2.y, b1.y);
        float o6 = fmaf(d, f3.x, b1.z), o7 = fmaf(d, f3.y, b1.w);
        if (HALF_OUT) {
            uint4 hv;
            __half2 h0 = __floats2half2_rn(fmaxf(o0, 0.f), fmaxf(o1, 0.f));
            __half2 h1 = __floats2half2_rn(fmaxf(o2, 0.f), fmaxf(o3, 0.f));
            __half2 h2 = __floats2half2_rn(fmaxf(o4, 0.f), fmaxf(o5, 0.f));
            __half2 h3 = __floats2half2_rn(fmaxf(o6, 0.f), fmaxf(o7, 0.f));
            hv.x = *reinterpret_cast<unsigned int*>(&h0);
            hv.y = *reinterpret_cast<unsigned int*>(&h1);
            hv.z = *reinterpret_cast<unsigned int*>(&h2);
            hv.w = *reinterpret_cast<unsigned int*>(&h3);
            ((uint4*)Sp)[(size_t)node * 8 + q] = hv;
        } else {
            float4* Sv = (float4*)Sp;
            Sv[(size_t)node * 16 + q * 2]     = make_float4(o0, o1, o2, o3);
            Sv[(size_t)node * 16 + q * 2 + 1] = make_float4(o4, o5, o6, o7);
        }
    }
}

// ---------------- Final: h = relu(S2); z = h@W3 + b3; log_softmax ----------------

__global__ void k_final(const float* __restrict__ S2, const float* __restrict__ W3,
                        const float* __restrict__ b3, float* __restrict__ out,
                        int n, int write_h) {
    __shared__ float w3s[64 * 16];
    __shared__ float b3s[16];
    for (int i = threadIdx.x; i < 64 * 16; i += blockDim.x) w3s[i] = W3[i];
    if (threadIdx.x < 16) b3s[threadIdx.x] = b3[threadIdx.x];
    __syncthreads();

    int row = blockIdx.x * blockDim.x + threadIdx.x;
    if (row >= n) return;

    float h[64];
    const float4* Sv = (const float4*)(S2 + (size_t)row * 64);
#pragma unroll
    for (int i = 0; i < 16; i++) {
        float4 v = Sv[i];
        h[4 * i + 0] = fmaxf(v.x, 0.0f);
        h[4 * i + 1] = fmaxf(v.y, 0.0f);
        h[4 * i + 2] = fmaxf(v.z, 0.0f);
        h[4 * i + 3] = fmaxf(v.w, 0.0f);
    }

    if (write_h) {
        float4* Hv = (float4*)(out + (size_t)n * 16 + (size_t)row * 64);
#pragma unroll
        for (int i = 0; i < 16; i++) {
            float4 v;
            v.x = h[4 * i + 0]; v.y = h[4 * i + 1];
            v.z = h[4 * i + 2]; v.w = h[4 * i + 3];
            Hv[i] = v;
        }
    }

    float z[16];
#pragma unroll
    for (int j = 0; j < 16; j++) z[j] = b3s[j];
#pragma unroll
    for (int k = 0; k < 64; k++) {
        float xv = h[k];
#pragma unroll
        for (int j = 0; j < 16; j++) z[j] = fmaf(xv, w3s[k * 16 + j], z[j]);
    }

    float m = z[0];
#pragma unroll
    for (int j = 1; j < 16; j++) m = fmaxf(m, z[j]);
    float ssum = 0.0f;
#pragma unroll
    for (int j = 0; j < 16; j++) ssum += __expf(z[j] - m);
    float lse = m + __logf(ssum);
#pragma unroll
    for (int j = 0; j < 16; j++) out[(size_t)row * 16 + j] = z[j] - lse;
}

// ---------------- launch ----------------

extern "C" void kernel_launch(void* const* d_in, const int* in_sizes, int n_in,
                              void* d_out, int out_size) {
    const float* x  = (const float*)d_in[0];
    const int*   ei = (const int*)d_in[1];
    const float* W1 = (const float*)d_in[2];
    const float* b1 = (const float*)d_in[3];
    const float* W2 = (const float*)d_in[4];
    const float* b2 = (const float*)d_in[5];
    const float* W3 = (const float*)d_in[6];
    const float* b3 = (const float*)d_in[7];
    float* out = (float*)d_out;

    int n = in_sizes[0] / 64;
    int e = in_sizes[1] / 2;
    const int* src = ei;
    const int* dst = ei + e;
    int write_h = (out_size >= n * 80) ? 1 : 0;

    void* cnt_p;  cudaGetSymbolAddress(&cnt_p,  g_count);
    void* flag_p; cudaGetSymbolAddress(&flag_p, g_flag);
    __half* G  = nullptr; cudaGetSymbolAddress((void**)&G,  g_Gh);
    __half* S1 = nullptr; cudaGetSymbolAddress((void**)&S1, g_S1h);
    float*  S2 = nullptr; cudaGetSymbolAddress((void**)&S2, g_S2);

    int nb = (n + 4095) / 4096;
    int e4blocks = ((e + 3) / 4 + 255) / 256;

    cudaMemsetAsync(cnt_p,  0, (size_t)n * sizeof(int));
    cudaMemsetAsync(flag_p, 0, 32 * sizeof(int));
    k_count<<<e4blocks, 256>>>(dst, e);
    k_scan<<<nb, 1024>>>(n);
    k_fill<<<e4blocks, 256>>>(src, dst, e);

    k_gemm_mma<false><<<296, 256>>>(x, W1, G, n);
    k_agg<true><<<(n * 32 + 255) / 256, 256>>>(G, b1, S1, n);
    k_gemm_mma<true><<<296, 256>>>(S1, W2, G, n);
    k_agg<false><<<(n * 32 + 255) / 256, 256>>>(G, b2, S2, n);
    k_final<<<(n + 255) / 256, 256>>>(S2, W3, b3, out, n, write_h);
}

// round 8
// speedup vs baseline: 1.2140x; 1.1013x over previous
#include <cuda_runtime.h>
#include <cuda_fp16.h>
#include <math.h>

// 3-layer GCN. Pull-style aggregation over a per-launch CSR (no feature atomics).
//   Xd = half(dis*X)  (prep);  G = Xd @ W  (pure fp16 HMMA GEMM, fp32 accum)
//   S[i] = b + dis[i] * (G[i] + sum_{dst=i} G[src])   (fp32 accum)
//   agg1 stores half(dis*relu(S1))  -> feeds GEMM2 directly.
//   out = log_softmax(relu(S2) @ W3 + b3), plus h = relu(S2)

#define MAX_N 100000
#define MAX_E 1600000
#define NPAD  100352

__device__ int      g_count[NPAD];
__device__ int      g_rowstart[NPAD];
__device__ int      g_cursor[NPAD];
__device__ float    g_dis[NPAD];
__device__ int      g_sums[32];
__device__ int      g_flag[32];
__device__ int      g_esrc[MAX_E];
__device__ __half   g_Xd[MAX_N * 64];
__device__ __half   g_Gh[MAX_N * 64];
__device__ __half   g_S1h[MAX_N * 64];
__device__ float    g_S2[MAX_N * 64];
__device__ unsigned g_Wf1[2048];
__device__ unsigned g_Wf2[2048];

typedef unsigned long long ull;

__device__ __forceinline__ void fadd2(ull& a, ull b) {
    asm("add.rn.f32x2 %0, %0, %1;" : "+l"(a) : "l"(b));
}
__device__ __forceinline__ ull h2_to_f2(unsigned int h) {
    __half2 hh = *reinterpret_cast<__half2*>(&h);
    float2 f = __half22float2(hh);
    return *reinterpret_cast<ull*>(&f);
}

// ---------------- CSR build ----------------

__global__ void k_count(const int* __restrict__ dst, int e) {
    int i4 = (blockIdx.x * blockDim.x + threadIdx.x) * 4;
    if (i4 + 3 < e) {
        int4 d = *(const int4*)&dst[i4];
        atomicAdd(&g_count[d.x], 1);
        atomicAdd(&g_count[d.y], 1);
        atomicAdd(&g_count[d.z], 1);
        atomicAdd(&g_count[d.w], 1);
    } else {
        for (int i = i4; i < e; i++) atomicAdd(&g_count[dst[i]], 1);
    }
}

__global__ void k_scan(int n) {
    __shared__ int sh[1024];
    __shared__ int s_prev;
    int b = blockIdx.x, t = threadIdx.x;
    int base = b * 4096 + t * 4;
    int v0 = 0, v1 = 0, v2 = 0, v3 = 0;
    if (base + 3 < n) {
        int4 v = *(const int4*)&g_count[base];
        v0 = v.x; v1 = v.y; v2 = v.z; v3 = v.w;
    } else {
        if (base     < n) v0 = g_count[base];
        if (base + 1 < n) v1 = g_count[base + 1];
        if (base + 2 < n) v2 = g_count[base + 2];
    }
    int local = v0 + v1 + v2 + v3;
    sh[t] = local;
    __syncthreads();
    for (int off = 1; off < 1024; off <<= 1) {
        int x = (t >= off) ? sh[t - off] : 0;
        __syncthreads();
        sh[t] += x;
        __syncthreads();
    }
    if (t == 1023) {
        g_sums[b] = sh[1023];
        __threadfence();
        atomicExch(&g_flag[b], 1);
    }
    if (t < 32) {
        int p = 0;
        for (int i = t; i < b; i += 32) {
            while (atomicAdd(&g_flag[i], 0) == 0) { }
            p += atomicAdd(&g_sums[i], 0);
        }
#pragma unroll
        for (int o = 16; o; o >>= 1) p += __shfl_xor_sync(0xffffffffu, p, o);
        if (t == 0) s_prev = p;
    }
    int excl = sh[t] - local;
    __syncthreads();
    int run = s_prev + excl;
    if (base < n) {
        g_rowstart[base] = run; g_cursor[base] = run;
        g_dis[base] = rsqrtf((float)(v0 + 1)); run += v0;
    }
    if (base + 1 < n) {
        g_rowstart[base + 1] = run; g_cursor[base + 1] = run;
        g_dis[base + 1] = rsqrtf((float)(v1 + 1)); run += v1;
    }
    if (base + 2 < n) {
        g_rowstart[base + 2] = run; g_cursor[base + 2] = run;
        g_dis[base + 2] = rsqrtf((float)(v2 + 1)); run += v2;
    }
    if (base + 3 < n) {
        g_rowstart[base + 3] = run; g_cursor[base + 3] = run;
        g_dis[base + 3] = rsqrtf((float)(v3 + 1));
    }
}

__global__ void k_fill(const int* __restrict__ src, const int* __restrict__ dst, int e) {
    int i4 = (blockIdx.x * blockDim.x + threadIdx.x) * 4;
    if (i4 + 3 < e) {
        int4 s = *(const int4*)&src[i4];
        int4 d = *(const int4*)&dst[i4];
        g_esrc[atomicAdd(&g_cursor[d.x], 1)] = s.x;
        g_esrc[atomicAdd(&g_cursor[d.y], 1)] = s.y;
        g_esrc[atomicAdd(&g_cursor[d.z], 1)] = s.z;
        g_esrc[atomicAdd(&g_cursor[d.w], 1)] = s.w;
    } else {
        for (int i = i4; i < e; i++)
            g_esrc[atomicAdd(&g_cursor[dst[i]], 1)] = src[i];
    }
}

// ---------------- prep: Xd = half(dis * X) ----------------

__global__ void k_prep_x(const float* __restrict__ X, __half* __restrict__ Xd, int n) {
    int i = blockIdx.x * blockDim.x + threadIdx.x;   // one float4 per thread
    if (i >= n * 16) return;
    int row = i >> 4;
    float d = g_dis[row];
    float4 v = ((const float4*)X)[i];
    __half2 h0 = __floats2half2_rn(v.x * d, v.y * d);
    __half2 h1 = __floats2half2_rn(v.z * d, v.w * d);
    uint2 o;
    o.x = *reinterpret_cast<unsigned*>(&h0);
    o.y = *reinterpret_cast<unsigned*>(&h1);
    ((uint2*)Xd)[i] = o;
}

// ---------------- prep: W -> fragment-ordered half2 array ----------------
// Wf flat layout: flat = (i>>2)*128 + lane*4 + (i&3), i = (ks*8+nt)*2 + p.
// value = half2(W[k][nn], W[k+1][nn]), k = ks*16 + (lane&3)*2 + p*8, nn = nt*8 + lane/4.

__global__ void k_prep_w(const float* __restrict__ W, unsigned* __restrict__ Wf) {
    int tid = threadIdx.x;
#pragma unroll
    for (int m = 0; m < 8; m++) {
        int flat = tid + m * 256;
        int j    = flat >> 7;
        int rem  = flat & 127;
        int lane = rem >> 2;
        int q    = rem & 3;
        int i    = j * 4 + q;
        int p  = i & 1;
        int nt = (i >> 1) & 7;
        int ks = i >> 4;
        int k  = ks * 16 + (lane & 3) * 2 + p * 8;
        int nn = nt * 8 + (lane >> 2);
        __half2 h = __floats2half2_rn(W[k * 64 + nn], W[(k + 1) * 64 + nn]);
        Wf[flat] = *reinterpret_cast<unsigned*>(&h);
    }
}

// ---------------- GEMM (tensor core, pure fp16 in): G = A @ W ----------------
// Block 256 thr / 8 warps, tile 128 rows. Double-buffered cp.async staging with
// XOR-chunk swizzle (conflict-free A-fragment LDS.32). B fragments: 16 coalesced
// LDG.128 from the prepacked Wf. Per warp: 32 HMMA m16n8k16 per tile.

__global__ void __launch_bounds__(256)
k_gemm_mma(const __half* __restrict__ A, const unsigned* __restrict__ Wf,
           __half* __restrict__ G, int n) {
    __shared__ __half xs[2][128 * 64];   // 16 KB each

    int tid  = threadIdx.x;
    int lane = tid & 31;
    int w    = tid >> 5;

    unsigned bfr[64];
    {
        uint4* b4 = (uint4*)bfr;
        const uint4* Wf4 = (const uint4*)Wf;
#pragma unroll
        for (int i = 0; i < 16; i++) b4[i] = Wf4[i * 32 + lane];
    }

    int ntiles = (n + 127) >> 7;
    int q = lane >> 2;
    int t = lane & 3;
    int ar = w * 16 + q;

    // staging: 1024 chunks of 16B per tile; thread handles chunks tid + j*256.
    auto stage = [&](int tile, int buf) {
#pragma unroll
        for (int j = 0; j < 4; j++) {
            int c   = tid + j * 256;
            int row = c >> 3;
            int ch  = c & 7;
            int grow = (tile << 7) + row;
            const __half* src = A + (size_t)grow * 64 + ch * 8;
            unsigned dst = (unsigned)__cvta_generic_to_shared(
                &xs[buf][row * 64 + ((ch ^ (row & 7)) << 3)]);
            int sz = (grow < n) ? 16 : 0;
            asm volatile("cp.async.cg.shared.global [%0], [%1], 16, %2;"
                         :: "r"(dst), "l"(src), "r"(sz));
        }
        asm volatile("cp.async.commit_group;");
    };

    int tile = blockIdx.x;
    if (tile < ntiles) stage(tile, 0);
    int buf = 0;

    for (; tile < ntiles; tile += gridDim.x) {
        asm volatile("cp.async.wait_group 0;");
        __syncthreads();

        int tn = tile + gridDim.x;
        if (tn < ntiles) stage(tn, buf ^ 1);

        float c[8][4];
#pragma unroll
        for (int nt = 0; nt < 8; nt++) {
            c[nt][0] = 0.f; c[nt][1] = 0.f; c[nt][2] = 0.f; c[nt][3] = 0.f;
        }

        const __half* xb = xs[buf];
#pragma unroll
        for (int ks = 0; ks < 4; ks++) {
            int base0 = ar * 64 + (((2 * ks)     ^ q) << 3) + 2 * t;
            int base1 = ar * 64 + (((2 * ks + 1) ^ q) << 3) + 2 * t;
            unsigned a0 = *reinterpret_cast<const unsigned*>(&xb[base0]);
            unsigned a1 = *reinterpret_cast<const unsigned*>(&xb[base0 + 8 * 64]);
            unsigned a2 = *reinterpret_cast<const unsigned*>(&xb[base1]);
            unsigned a3 = *reinterpret_cast<const unsigned*>(&xb[base1 + 8 * 64]);
#pragma unroll
            for (int nt = 0; nt < 8; nt++) {
                int bi = (ks * 8 + nt) * 2;
                asm volatile(
                    "mma.sync.aligned.m16n8k16.row.col.f32.f16.f16.f32 "
                    "{%0,%1,%2,%3}, {%4,%5,%6,%7}, {%8,%9}, {%0,%1,%2,%3};"
                    : "+f"(c[nt][0]), "+f"(c[nt][1]), "+f"(c[nt][2]), "+f"(c[nt][3])
                    : "r"(a0), "r"(a1), "r"(a2), "r"(a3),
                      "r"(bfr[bi]), "r"(bfr[bi + 1]));
            }
        }

        int row0 = (tile << 7) + w * 16 + q;
        int coln = t * 2;
#pragma unroll
        for (int nt = 0; nt < 8; nt++) {
            __half2 hlo = __floats2half2_rn(c[nt][0], c[nt][1]);
            __half2 hhi = __floats2half2_rn(c[nt][2], c[nt][3]);
            if (row0 < n)
                *reinterpret_cast<unsigned*>(&G[(size_t)row0 * 64 + nt * 8 + coln]) =
                    *reinterpret_cast<unsigned*>(&hlo);
            if (row0 + 8 < n)
                *reinterpret_cast<unsigned*>(&G[(size_t)(row0 + 8) * 64 + nt * 8 + coln]) =
                    *reinterpret_cast<unsigned*>(&hhi);
        }
        buf ^= 1;
    }
}

// ---------------- Aggregation: 1 warp/node; 8 lanes x 16B, 4-edge ILP ----------------
// HALF_OUT: store half(dis * relu(S)) (layer-1, feeds GEMM2). Else fp32 S.

template <bool HALF_OUT>
__global__ void k_agg(const __half* __restrict__ G, const float* __restrict__ bias,
                      void* __restrict__ Sp, int n) {
    int warp = (blockIdx.x * blockDim.x + threadIdx.x) >> 5;
    if (warp >= n) return;
    int node = warp;
    int lane = threadIdx.x & 31;
    int q  = lane & 7;
    int pe = lane >> 3;

    const uint4* __restrict__ Gv = (const uint4*)G;
    ull acc0 = 0, acc1 = 0, acc2 = 0, acc3 = 0;

    if (pe == 0) {
        uint4 v = Gv[(size_t)node * 8 + q];   // self-loop term
        acc0 = h2_to_f2(v.x); acc1 = h2_to_f2(v.y);
        acc2 = h2_to_f2(v.z); acc3 = h2_to_f2(v.w);
    }

    int s   = g_rowstart[node];
    int end = s + g_count[node];
    for (int p = s + pe; p < end; p += 4) {
        int j = g_esrc[p];
        uint4 v = Gv[(size_t)j * 8 + q];
        fadd2(acc0, h2_to_f2(v.x));
        fadd2(acc1, h2_to_f2(v.y));
        fadd2(acc2, h2_to_f2(v.z));
        fadd2(acc3, h2_to_f2(v.w));
    }

#pragma unroll
    for (int o = 8; o <= 16; o <<= 1) {
        fadd2(acc0, __shfl_xor_sync(0xffffffffu, acc0, o));
        fadd2(acc1, __shfl_xor_sync(0xffffffffu, acc1, o));
        fadd2(acc2, __shfl_xor_sync(0xffffffffu, acc2, o));
        fadd2(acc3, __shfl_xor_sync(0xffffffffu, acc3, o));
    }

    if (pe == 0) {
        float d = g_dis[node];
        float2 f0 = *reinterpret_cast<float2*>(&acc0);
        float2 f1 = *reinterpret_cast<float2*>(&acc1);
        float2 f2 = *reinterpret_cast<float2*>(&acc2);
        float2 f3 = *reinterpret_cast<float2*>(&acc3);
        const float4* Bv = (const float4*)bias;
        float4 b0 = Bv[q * 2], b1 = Bv[q * 2 + 1];
        float o0 = fmaf(d, f0.x, b0.x), o1 = fmaf(d, f0.y, b0.y);
        float o2 = fmaf(d, f1.x, b0.z), o3 = fmaf(d, f1.y, b0.w);
        float o4 = fmaf(d, f2.x, b1.x), o5 = fmaf(d, f2.y, b1.y);
        float o6 = fmaf(d, f3.x, b1.z), o7 = fmaf(d, f3.y, b1.w);
        if (HALF_OUT) {
            // store dis * relu(S1): ready-to-use GEMM2 input
            uint4 hv;
            __half2 h0 = __floats2half2_rn(d * fmaxf(o0, 0.f), d * fmaxf(o1, 0.f));
            __half2 h1 = __floats2half2_rn(d * fmaxf(o2, 0.f), d * fmaxf(o3, 0.f));
            __half2 h2 = __floats2half2_rn(d * fmaxf(o4, 0.f), d * fmaxf(o5, 0.f));
            __half2 h3 = __floats2half2_rn(d * fmaxf(o6, 0.f), d * fmaxf(o7, 0.f));
            hv.x = *reinterpret_cast<unsigned int*>(&h0);
            hv.y = *reinterpret_cast<unsigned int*>(&h1);
            hv.z = *reinterpret_cast<unsigned int*>(&h2);
            hv.w = *reinterpret_cast<unsigned int*>(&h3);
            ((uint4*)Sp)[(size_t)node * 8 + q] = hv;
        } else {
            float4* Sv = (float4*)Sp;
            Sv[(size_t)node * 16 + q * 2]     = make_float4(o0, o1, o2, o3);
            Sv[(size_t)node * 16 + q * 2 + 1] = make_float4(o4, o5, o6, o7);
        }
    }
}

// ---------------- Final: h = relu(S2); z = h@W3 + b3; log_softmax ----------------

__global__ void k_final(const float* __restrict__ S2, const float* __restrict__ W3,
                        const float* __restrict__ b3, float* __restrict__ out,
                        int n, int write_h) {
    __shared__ float w3s[64 * 16];
    __shared__ float b3s[16];
    for (int i = threadIdx.x; i < 64 * 16; i += blockDim.x) w3s[i] = W3[i];
    if (threadIdx.x < 16) b3s[threadIdx.x] = b3[threadIdx.x];
    __syncthreads();

    int row = blockIdx.x * blockDim.x + threadIdx.x;
    if (row >= n) return;

    float h[64];
    const float4* Sv = (const float4*)(S2 + (size_t)row * 64);
#pragma unroll
    for (int i = 0; i < 16; i++) {
        float4 v = Sv[i];
        h[4 * i + 0] = fmaxf(v.x, 0.0f);
        h[4 * i + 1] = fmaxf(v.y, 0.0f);
        h[4 * i + 2] = fmaxf(v.z, 0.0f);
        h[4 * i + 3] = fmaxf(v.w, 0.0f);
    }

    if (write_h) {
        float4* Hv = (float4*)(out + (size_t)n * 16 + (size_t)row * 64);
#pragma unroll
        for (int i = 0; i < 16; i++) {
            float4 v;
            v.x = h[4 * i + 0]; v.y = h[4 * i + 1];
            v.z = h[4 * i + 2]; v.w = h[4 * i + 3];
            Hv[i] = v;
        }
    }

    float z[16];
#pragma unroll
    for (int j = 0; j < 16; j++) z[j] = b3s[j];
#pragma unroll
    for (int k = 0; k < 64; k++) {
        float xv = h[k];
#pragma unroll
        for (int j = 0; j < 16; j++) z[j] = fmaf(xv, w3s[k * 16 + j], z[j]);
    }

    float m = z[0];
#pragma unroll
    for (int j = 1; j < 16; j++) m = fmaxf(m, z[j]);
    float ssum = 0.0f;
#pragma unroll
    for (int j = 0; j < 16; j++) ssum += __expf(z[j] - m);
    float lse = m + __logf(ssum);
#pragma unroll
    for (int j = 0; j < 16; j++) out[(size_t)row * 16 + j] = z[j] - lse;
}

// ---------------- launch ----------------

extern "C" void kernel_launch(void* const* d_in, const int* in_sizes, int n_in,
                              void* d_out, int out_size) {
    const float* x  = (const float*)d_in[0];
    const int*   ei = (const int*)d_in[1];
    const float* W1 = (const float*)d_in[2];
    const float* b1 = (const float*)d_in[3];
    const float* W2 = (const float*)d_in[4];
    const float* b2 = (const float*)d_in[5];
    const float* W3 = (const float*)d_in[6];
    const float* b3 = (const float*)d_in[7];
    float* out = (float*)d_out;

    int n = in_sizes[0] / 64;
    int e = in_sizes[1] / 2;
    const int* src = ei;
    const int* dst = ei + e;
    int write_h = (out_size >= n * 80) ? 1 : 0;

    void* cnt_p;  cudaGetSymbolAddress(&cnt_p,  g_count);
    void* flag_p; cudaGetSymbolAddress(&flag_p, g_flag);
    __half* Xd = nullptr; cudaGetSymbolAddress((void**)&Xd, g_Xd);
    __half* G  = nullptr; cudaGetSymbolAddress((void**)&G,  g_Gh);
    __half* S1 = nullptr; cudaGetSymbolAddress((void**)&S1, g_S1h);
    float*  S2 = nullptr; cudaGetSymbolAddress((void**)&S2, g_S2);
    unsigned* Wf1 = nullptr; cudaGetSymbolAddress((void**)&Wf1, g_Wf1);
    unsigned* Wf2 = nullptr; cudaGetSymbolAddress((void**)&Wf2, g_Wf2);

    int nb = (n + 4095) / 4096;
    int e4blocks = ((e + 3) / 4 + 255) / 256;

    cudaMemsetAsync(cnt_p,  0, (size_t)n * sizeof(int));
    cudaMemsetAsync(flag_p, 0, 32 * sizeof(int));
    k_prep_w<<<1, 256>>>(W1, Wf1);
    k_prep_w<<<1, 256>>>(W2, Wf2);
    k_count<<<e4blocks, 256>>>(dst, e);
    k_scan<<<nb, 1024>>>(n);
    k_fill<<<e4blocks, 256>>>(src, dst, e);
    k_prep_x<<<(n * 16 + 255) / 256, 256>>>(x, Xd, n);

    k_gemm_mma<<<296, 256>>>(Xd, Wf1, G, n);
    k_agg<true><<<(n * 32 + 255) / 256, 256>>>(G, b1, S1, n);
    k_gemm_mma<<<296, 256>>>(S1, Wf2, G, n);
    k_agg<false><<<(n * 32 + 255) / 256, 256>>>(G, b2, S2, n);
    k_final<<<(n + 255) / 256, 256>>>(S2, W3, b3, out, n, write_h);
}